// round 2
// baseline (speedup 1.0000x reference)
#include <cuda_runtime.h>

#define T_   256
#define B_   8
#define U_   128
#define DE   512
#define H_   512
#define MENC (T_*B_)        // 2048 rows of enc_proj, row index = t*B + b
#define MDEC (B_*U_)        // 1024 rows of dec_proj, row index = b*U + u
#define MTOT (MENC + MDEC)  // 3072

// Scratch for projections: enc_proj rows [0,2048), dec_proj rows [2048,3072)
__device__ float g_proj[(size_t)MTOT * H_];

typedef unsigned long long ull;

__device__ __forceinline__ ull pk2(float x, float y) {
    ull r; asm("mov.b64 %0, {%1, %2};" : "=l"(r) : "f"(x), "f"(y)); return r;
}
__device__ __forceinline__ void upk2(ull v, float& x, float& y) {
    asm("mov.b64 {%0, %1}, %2;" : "=f"(x), "=f"(y) : "l"(v));
}
__device__ __forceinline__ ull ffma2(ull a, ull b, ull c) {
    ull d; asm("fma.rn.f32x2 %0, %1, %2, %3;" : "=l"(d) : "l"(a), "l"(b), "l"(c)); return d;
}
__device__ __forceinline__ float tanh_fast(float x) {
    float y; asm("tanh.approx.f32 %0, %1;" : "=f"(y) : "f"(x)); return y;
}

// ---------------------------------------------------------------------------
// Fused dual GEMM with packed FFMA2 + double-buffered smem.
// 64x64 tile, BK=16, 128 threads, 4(m) x 8(n) per thread (n packed in pairs).
// rows < 2048 -> enc @ W[:512] + bias ; rows >= 2048 -> dec @ W[512:]
// ---------------------------------------------------------------------------
__global__ __launch_bounds__(128) void gemm_kernel(
    const float* __restrict__ enc,   // (2048, 512)
    const float* __restrict__ dec,   // (1024, 512)
    const float* __restrict__ W,     // (1024, 512)
    const float* __restrict__ bias)  // (512)
{
    __shared__ float As[2][16][64];  // [buf][k][m]
    __shared__ float Bs[2][16][64];  // [buf][k][n]

    const int tid = threadIdx.x;
    const int tx = tid & 7;     // n-group (8 cols)
    const int ty = tid >> 3;    // m-group (4 rows), 0..15

    const int mBlock = blockIdx.y * 64;
    const int nBlock = blockIdx.x * 64;
    const bool isEnc = (mBlock < MENC);

    const float* A  = isEnc ? (enc + (size_t)mBlock * DE)
                            : (dec + (size_t)(mBlock - MENC) * DE);
    const float* Bm = W + (isEnc ? 0 : (size_t)DE * H_) + nBlock;

    // loader decomposition (2 float4 per thread per tile)
    const int am0 = (tid      ) >> 2, ak0 = ((tid      ) & 3) * 4;
    const int am1 = (tid + 128) >> 2, ak1 = ((tid + 128) & 3) * 4;
    const int bk0 = (tid      ) >> 4, bn0 = ((tid      ) & 15) * 4;
    const int bk1 = (tid + 128) >> 4, bn1 = ((tid + 128) & 15) * 4;

    ull acc[4][4];
#pragma unroll
    for (int i = 0; i < 4; i++)
#pragma unroll
        for (int j = 0; j < 4; j++) acc[i][j] = 0ull;

    // prologue: tile 0 -> buf 0
    {
        float4 a4 = *(const float4*)(A + (size_t)am0 * DE + ak0);
        As[0][ak0 + 0][am0] = a4.x; As[0][ak0 + 1][am0] = a4.y;
        As[0][ak0 + 2][am0] = a4.z; As[0][ak0 + 3][am0] = a4.w;
        float4 a5 = *(const float4*)(A + (size_t)am1 * DE + ak1);
        As[0][ak1 + 0][am1] = a5.x; As[0][ak1 + 1][am1] = a5.y;
        As[0][ak1 + 2][am1] = a5.z; As[0][ak1 + 3][am1] = a5.w;
        *(float4*)&Bs[0][bk0][bn0] = *(const float4*)(Bm + (size_t)bk0 * H_ + bn0);
        *(float4*)&Bs[0][bk1][bn1] = *(const float4*)(Bm + (size_t)bk1 * H_ + bn1);
    }
    __syncthreads();

    for (int it = 0; it < 32; ++it) {
        const int cur = it & 1;
        float4 an0, an1, bn4a, bn4b;
        if (it < 31) {
            const int k0 = (it + 1) * 16;
            an0  = *(const float4*)(A + (size_t)am0 * DE + k0 + ak0);
            an1  = *(const float4*)(A + (size_t)am1 * DE + k0 + ak1);
            bn4a = *(const float4*)(Bm + (size_t)(k0 + bk0) * H_ + bn0);
            bn4b = *(const float4*)(Bm + (size_t)(k0 + bk1) * H_ + bn1);
        }

#pragma unroll
        for (int k = 0; k < 16; k++) {
            float4 a4 = *(const float4*)&As[cur][k][ty * 4];
            float4 b0 = *(const float4*)&Bs[cur][k][tx * 8];
            float4 b1 = *(const float4*)&Bs[cur][k][tx * 8 + 4];
            ull bp0 = pk2(b0.x, b0.y);
            ull bp1 = pk2(b0.z, b0.w);
            ull bp2 = pk2(b1.x, b1.y);
            ull bp3 = pk2(b1.z, b1.w);
            ull ap;
            ap = pk2(a4.x, a4.x);
            acc[0][0] = ffma2(ap, bp0, acc[0][0]); acc[0][1] = ffma2(ap, bp1, acc[0][1]);
            acc[0][2] = ffma2(ap, bp2, acc[0][2]); acc[0][3] = ffma2(ap, bp3, acc[0][3]);
            ap = pk2(a4.y, a4.y);
            acc[1][0] = ffma2(ap, bp0, acc[1][0]); acc[1][1] = ffma2(ap, bp1, acc[1][1]);
            acc[1][2] = ffma2(ap, bp2, acc[1][2]); acc[1][3] = ffma2(ap, bp3, acc[1][3]);
            ap = pk2(a4.z, a4.z);
            acc[2][0] = ffma2(ap, bp0, acc[2][0]); acc[2][1] = ffma2(ap, bp1, acc[2][1]);
            acc[2][2] = ffma2(ap, bp2, acc[2][2]); acc[2][3] = ffma2(ap, bp3, acc[2][3]);
            ap = pk2(a4.w, a4.w);
            acc[3][0] = ffma2(ap, bp0, acc[3][0]); acc[3][1] = ffma2(ap, bp1, acc[3][1]);
            acc[3][2] = ffma2(ap, bp2, acc[3][2]); acc[3][3] = ffma2(ap, bp3, acc[3][3]);
        }

        if (it < 31) {
            const int nxt = cur ^ 1;
            As[nxt][ak0 + 0][am0] = an0.x; As[nxt][ak0 + 1][am0] = an0.y;
            As[nxt][ak0 + 2][am0] = an0.z; As[nxt][ak0 + 3][am0] = an0.w;
            As[nxt][ak1 + 0][am1] = an1.x; As[nxt][ak1 + 1][am1] = an1.y;
            As[nxt][ak1 + 2][am1] = an1.z; As[nxt][ak1 + 3][am1] = an1.w;
            *(float4*)&Bs[nxt][bk0][bn0] = bn4a;
            *(float4*)&Bs[nxt][bk1][bn1] = bn4b;
            __syncthreads();
        }
    }

    // epilogue
    float bv[8];
    if (isEnc) {
        float4 q0 = *(const float4*)(bias + nBlock + tx * 8);
        float4 q1 = *(const float4*)(bias + nBlock + tx * 8 + 4);
        bv[0] = q0.x; bv[1] = q0.y; bv[2] = q0.z; bv[3] = q0.w;
        bv[4] = q1.x; bv[5] = q1.y; bv[6] = q1.z; bv[7] = q1.w;
    } else {
#pragma unroll
        for (int j = 0; j < 8; j++) bv[j] = 0.0f;
    }

#pragma unroll
    for (int i = 0; i < 4; i++) {
        const int row = mBlock + ty * 4 + i;
        float o[8];
#pragma unroll
        for (int j = 0; j < 4; j++) upk2(acc[i][j], o[2 * j], o[2 * j + 1]);
#pragma unroll
        for (int j = 0; j < 8; j++) o[j] += bv[j];
        float* dst = g_proj + (size_t)row * H_ + nBlock + tx * 8;
        *(float4*)dst       = make_float4(o[0], o[1], o[2], o[3]);
        *(float4*)(dst + 4) = make_float4(o[4], o[5], o[6], o[7]);
    }
}

// ---------------------------------------------------------------------------
// Broadcast + tanh + write, t-tiled: block = (t-tile of 8, b).
// Each dec value read ONCE per block and reused for 8 t's -> L2 read traffic
// drops from 512 MB to 64 MB. enc rows cached in registers.
// 512 threads: 128 h4-lanes x 4 u-phases.
// ---------------------------------------------------------------------------
__global__ __launch_bounds__(512) void joint_kernel(float* __restrict__ out) {
    const int tt = blockIdx.x;          // 0..31
    const int b  = blockIdx.y;          // 0..7
    const int t0 = tt * 8;
    const int lane = threadIdx.x & 127; // h/4 position
    const int grp  = threadIdx.x >> 7;  // 0..3 (u phase)

    float4 e[8];
#pragma unroll
    for (int i = 0; i < 8; i++)
        e[i] = *((const float4*)(g_proj + (size_t)((t0 + i) * B_ + b) * H_) + lane);

    const float4* d4 = (const float4*)(g_proj + (size_t)MENC * H_ + (size_t)b * U_ * H_);
    float4* ob = (float4*)out + ((size_t)b * T_ + t0) * U_ * (H_ / 4);

#pragma unroll 2
    for (int ui = 0; ui < U_ / 4; ui++) {
        const int u = grp + 4 * ui;
        const float4 d = d4[(size_t)u * (H_ / 4) + lane];
#pragma unroll
        for (int t = 0; t < 8; t++) {
            float4 r;
            r.x = tanh_fast(e[t].x + d.x);
            r.y = tanh_fast(e[t].y + d.y);
            r.z = tanh_fast(e[t].z + d.z);
            r.w = tanh_fast(e[t].w + d.w);
            ob[((size_t)t * U_ + u) * (H_ / 4) + lane] = r;
        }
    }
}

// ---------------------------------------------------------------------------
// fake_src_lengths[b] = ceil(sum(mask[b,:] != padding_idx) / DOWNSAMPLE), DOWNSAMPLE=1
// ---------------------------------------------------------------------------
__global__ void lengths_kernel(const unsigned char* __restrict__ mask,
                               const int* __restrict__ pidx_p,
                               float* __restrict__ out_len) {
    const int b = blockIdx.x;
    const int pidx = pidx_p[0];
    __shared__ int cnt;
    if (threadIdx.x == 0) cnt = 0;
    __syncthreads();
    int tok = (int)mask[b * T_ + threadIdx.x];
    int c = (tok != pidx) ? 1 : 0;
    for (int off = 16; off > 0; off >>= 1)
        c += __shfl_down_sync(0xFFFFFFFFu, c, off);
    if ((threadIdx.x & 31) == 0) atomicAdd(&cnt, c);
    __syncthreads();
    if (threadIdx.x == 0) out_len[b] = (float)cnt;
}

extern "C" void kernel_launch(void* const* d_in, const int* in_sizes, int n_in,
                              void* d_out, int out_size) {
    const float*         enc  = (const float*)d_in[0];          // (T,B,De)
    const float*         dec  = (const float*)d_in[1];          // (B,U,Dd)
    const unsigned char* mask = (const unsigned char*)d_in[2];  // (B,T) bool
    const float*         W    = (const float*)d_in[3];          // (1024, 512)
    const float*         bias = (const float*)d_in[4];          // (512)
    const int*           pidx = (const int*)d_in[5];            // scalar
    float* out = (float*)d_out;

    dim3 gGrid(H_ / 64, MTOT / 64);   // (8, 48) = 384 blocks
    gemm_kernel<<<gGrid, 128>>>(enc, dec, W, bias);

    dim3 jGrid(T_ / 8, B_);           // (32, 8) = 256 blocks
    joint_kernel<<<jGrid, 512>>>(out);

    const long long hsize = (long long)B_ * T_ * U_ * H_;  // 134217728
    if ((long long)out_size > hsize) {
        lengths_kernel<<<B_, T_>>>(mask, pidx, out + hsize);
    }
    (void)in_sizes; (void)n_in;
}